// round 15
// baseline (speedup 1.0000x reference)
#include <cuda_runtime.h>
#include <cuda_bf16.h>
#include <math.h>

#define B_    32
#define S_    2048
#define H_    256
#define V_    50000
#define OOV_  12
#define VEXT_ 50012
#define M_    (B_*S_)
#define KD_   512
#define XD_   768
#define TOT_  (V_ + S_)
#define NCH_  13

#define OFF_STATE 1600384
#define OFF_W     1608576

// ---------------- scratch ----------------
__device__ __align__(16) float g_xT[XD_*B_];
__device__ __align__(16) float g_hT[H_*B_];
__device__ __align__(16) float g_gx[768*B_];
__device__ __align__(16) float g_gh[768*B_];
__device__ __align__(16) float g_state[B_*H_];
__device__ __align__(16) float g_score_g[B_*V_];
__device__ __align__(16) float g_score_c[M_];
__device__ __align__(16) float g_pacc[M_];
__device__ __align__(16) float g_prob_c[M_];
__device__            int   g_counts[VEXT_];
__device__            int   g_rs[B_];
__device__ __align__(16) float g_rowsums[B_*VEXT_];
__device__ __align__(16) __nv_bfloat16 g_WcH[H_*KD_];
__device__ __align__(16) __nv_bfloat16 g_WcL[H_*KD_];
__device__ float g_pm[B_*NCH_];
__device__ float g_ps[B_*NCH_];
__device__ float g_gm[B_];
__device__ float g_ginv[B_];
__device__ int   g_mcount;
__device__ int   g_mlist[8192];
__device__ float g_mval[8192];

__device__ __forceinline__ float sigm(float x) { return 1.f / (1.f + expf(-x)); }

__device__ __forceinline__ void hmma16816(float* c, const unsigned* a, const unsigned* b) {
    asm volatile(
        "mma.sync.aligned.m16n8k16.row.col.f32.bf16.bf16.f32 "
        "{%0,%1,%2,%3}, {%4,%5,%6,%7}, {%8,%9}, {%0,%1,%2,%3};"
        : "+f"(c[0]), "+f"(c[1]), "+f"(c[2]), "+f"(c[3])
        : "r"(a[0]), "r"(a[1]), "r"(a[2]), "r"(a[3]), "r"(b[0]), "r"(b[1]));
}
__device__ __forceinline__ unsigned smem_u32(const void* p) {
    unsigned a;
    asm("{ .reg .u64 t; cvta.to.shared.u64 t, %1; cvt.u32.u64 %0, t; }" : "=r"(a) : "l"(p));
    return a;
}
__device__ __forceinline__ void cp16(unsigned dst, const void* src) {
    asm volatile("cp.async.cg.shared.global [%0], [%1], 16;"
                 :: "r"(dst), "l"(__cvta_generic_to_global(src)) : "memory");
}
#define CP_COMMIT() asm volatile("cp.async.commit_group;" ::: "memory")
#define CP_WAIT(n)  asm volatile("cp.async.wait_group %0;" :: "n"(n) : "memory")
#define LDSM4(r0, r1, r2, r3, addr) \
    asm volatile("ldmatrix.sync.aligned.m8n8.x4.shared.b16 {%0,%1,%2,%3}, [%4];" \
                 : "=r"(r0), "=r"(r1), "=r"(r2), "=r"(r3) : "r"(addr))

// ---- K0: zero scratch + Wc split + gathers ----
__global__ void k_prep(const int* __restrict__ input_idx, const float* __restrict__ embed,
                       const float* __restrict__ weighted, const float* __restrict__ prev_state,
                       const float* __restrict__ Wc_w, float* __restrict__ out)
{
    const int N0 = VEXT_;
    const int N1 = B_*VEXT_;
    const int N2 = H_*KD_;
    const int N3 = XD_*B_;
    const int N4 = H_*B_;
    const int N5 = B_*512;
    const int N6 = B_;
    const int N7 = M_;
    const int total = N0 + N1 + N2 + N3 + N4 + N5 + N6 + N7 + 1;
    for (int gid = blockIdx.x*blockDim.x + threadIdx.x; gid < total; gid += gridDim.x*blockDim.x) {
        int i = gid;
        if (i < N0) { g_counts[i] = 0; continue; }
        i -= N0;
        if (i < N1) { g_rowsums[i] = 0.f; continue; }
        i -= N1;
        if (i < N2) {
            float x = Wc_w[i];
            __nv_bfloat16 h = __float2bfloat16(x);
            g_WcH[i] = h;
            g_WcL[i] = __float2bfloat16(x - __bfloat162float(h));
            continue;
        }
        i -= N2;
        if (i < N3) {
            int k = i >> 5; int b = i & 31;
            g_xT[i] = (k < 256) ? embed[(size_t)input_idx[b]*256 + k] : weighted[b*512 + (k-256)];
            continue;
        }
        i -= N3;
        if (i < N4) { int k = i >> 5; int b = i & 31; g_hT[i] = prev_state[b*H_ + k]; continue; }
        i -= N4;
        if (i < N5) { out[OFF_W + i] = 0.f; continue; }
        i -= N5;
        if (i < N6) { g_rs[i] = 0; continue; }
        i -= N6;
        if (i < N7) { g_pacc[i] = 0.f; continue; }
        g_mcount = 0;
    }
}

// ---- histogram + per-row match + FINAL score_c (tanh of cross-CTA partials) ----
__global__ void k_counts(const int* __restrict__ eidx, const int* __restrict__ input_idx) {
    int gid = blockIdx.x*blockDim.x + threadIdx.x;
    if (gid < M_) {
        int idx = eidx[gid];
        atomicAdd(&g_counts[idx], 1);
        int b = gid >> 11;
        if (idx == input_idx[b]) atomicAdd(&g_rs[b], 1);
        float v = tanhf(g_pacc[gid]);
        if (idx == 0) v -= 1000.f;
        g_score_c[gid] = v;
    }
}

// ---- GRU gemms ----
__global__ void k_gru_gemm(const float* __restrict__ w_ih, const float* __restrict__ w_hh) {
    const int tid = threadIdx.x;
    const int b = tid & 31;
    const int j = blockIdx.x*8 + (tid >> 5);
    if (blockIdx.y == 0) {
        const float4* wr = (const float4*)(w_ih + (size_t)j*XD_);
        float acc = 0.f;
        #pragma unroll 8
        for (int k4 = 0; k4 < XD_/4; ++k4) {
            float4 wv = wr[k4];
            int k = k4*4;
            acc += wv.x*g_xT[(k+0)*32+b] + wv.y*g_xT[(k+1)*32+b]
                 + wv.z*g_xT[(k+2)*32+b] + wv.w*g_xT[(k+3)*32+b];
        }
        g_gx[j*32+b] = acc;
    } else {
        const float4* wr = (const float4*)(w_hh + (size_t)j*H_);
        float acc = 0.f;
        #pragma unroll 8
        for (int k4 = 0; k4 < H_/4; ++k4) {
            float4 wv = wr[k4];
            int k = k4*4;
            acc += wv.x*g_hT[(k+0)*32+b] + wv.y*g_hT[(k+1)*32+b]
                 + wv.z*g_hT[(k+2)*32+b] + wv.w*g_hT[(k+3)*32+b];
        }
        g_gh[j*32+b] = acc;
    }
}

// ---- gates ----
__global__ void k_gates(const float* __restrict__ b_ih, const float* __restrict__ b_hh,
                        const float* __restrict__ prev_state, float* __restrict__ out)
{
    const int b = blockIdx.x, h = threadIdx.x;
    float xr = g_gx[h*32+b]        + b_ih[h];
    float xz = g_gx[(256+h)*32+b]  + b_ih[256+h];
    float xn = g_gx[(512+h)*32+b]  + b_ih[512+h];
    float hr = g_gh[h*32+b]        + b_hh[h];
    float hz = g_gh[(256+h)*32+b]  + b_hh[256+h];
    float hn = g_gh[(512+h)*32+b]  + b_hh[512+h];
    float r = sigm(xr + hr);
    float z = sigm(xz + hz);
    float n = tanhf(xn + r*hn);
    float st = (1.f - z)*n + z*prev_state[b*H_+h];
    g_state[b*H_+h] = st;
    out[OFF_STATE + b*H_ + h] = st;
}

// ---- score_g: smem-staged coalesced W ----
__global__ __launch_bounds__(256) void k_score_g(const float* __restrict__ Wo_w,
                                                 const float* __restrict__ Wo_b)
{
    extern __shared__ __align__(16) float sg[];
    float* st = sg;                       // [256k][32b]
    float4* sw4 = (float4*)(sg + 8192);   // [64v][64 float4]
    const int tid = threadIdx.x;
    const int v0 = blockIdx.x * 64;

    for (int i = tid; i < 8192; i += 256) {
        int k = i >> 5, b = i & 31;
        st[i] = g_state[b*H_ + k];
    }
    for (int i = tid; i < 4096; i += 256) {
        int row = i >> 6, seg = i & 63;
        int v = v0 + row;
        sw4[i] = (v < V_) ? ((const float4*)(Wo_w + (size_t)v*H_))[seg]
                          : make_float4(0.f, 0.f, 0.f, 0.f);
    }
    __syncthreads();

    const int w = tid >> 5;
    const int lane = tid & 31;
    if (v0 + w*8 >= V_) return;

    float a[8];
    #pragma unroll
    for (int r = 0; r < 8; ++r) a[r] = 0.f;

    #pragma unroll 4
    for (int k4 = 0; k4 < 64; ++k4) {
        float s0 = st[(k4*4+0)*32 + lane];
        float s1 = st[(k4*4+1)*32 + lane];
        float s2 = st[(k4*4+2)*32 + lane];
        float s3 = st[(k4*4+3)*32 + lane];
        #pragma unroll
        for (int r = 0; r < 8; ++r) {
            float4 wv = sw4[(w*8+r)*64 + k4];
            a[r] += wv.x*s0 + wv.y*s1 + wv.z*s2 + wv.w*s3;
        }
    }
    int vb = v0 + w*8;
    float4 o0, o1;
    o0.x = a[0] + Wo_b[vb+0]; o0.y = a[1] + Wo_b[vb+1];
    o0.z = a[2] + Wo_b[vb+2]; o0.w = a[3] + Wo_b[vb+3];
    o1.x = a[4] + Wo_b[vb+4]; o1.y = a[5] + Wo_b[vb+5];
    o1.z = a[6] + Wo_b[vb+6]; o1.w = a[7] + Wo_b[vb+7];
    *(float4*)(g_score_g + (size_t)lane*V_ + vb)     = o0;
    *(float4*)(g_score_g + (size_t)lane*V_ + vb + 4) = o1;
}
#define SG_SMEM 98304

// ---- K4: 2-CTA/SM HMMA bf16-split score_c partials, ldmatrix + 1-barrier pipeline ----
// CTA 128(m) x 128(n), K=512 in 16 chunks of 32. 256 threads, 8 warps = 2(m)x4(n),
// warp tile 64x32. A double-buffered (cvt post-barrier), B triple-buffered cp.async.
#define OAH_ 0        // 2 bufs x 10240
#define OAL_ 20480    // 2 bufs x 10240
#define OBH_ 40960    // 3 bufs x 10240
#define OBL_ 71680    // 3 bufs x 10240
#define OST_ 102400
#define OBI_ 102912
#define OP_  103424
#define SC_SMEM 103936

__global__ __launch_bounds__(256, 2) void k_score_c(const float* __restrict__ enc,
                                                    const float* __restrict__ wcb)
{
    extern __shared__ __align__(16) char sm[];
    const unsigned sbase = smem_u32(sm);
    const int tid = threadIdx.x;
    const int lane = tid & 31;
    const int wid = tid >> 5;
    const int wm = wid >> 2;          // 0..1 : rows wm*64
    const int wn = wid & 3;           // 0..3 : cols wn*32
    const int q2 = (lane & 3) * 2;
    const int m0  = (blockIdx.x >> 1) * 128;
    const int n0c = (blockIdx.x & 1) * 128;
    const int b   = m0 >> 11;

    float* s_state = (float*)(sm + OST_);
    float* s_bias  = (float*)(sm + OBI_);
    float* s_p     = (float*)(sm + OP_);
    if (tid < 128) {
        s_state[tid] = g_state[b*H_ + n0c + tid];
        s_bias[tid]  = wcb[n0c + tid];
        s_p[tid] = 0.f;
    }

    float acc[4][4][4];
    #pragma unroll
    for (int mt = 0; mt < 4; ++mt)
        #pragma unroll
        for (int nt = 0; nt < 4; ++nt)
            #pragma unroll
            for (int e = 0; e < 4; ++e) acc[mt][nt][e] = 0.f;

    // ldmatrix lane address offsets (bytes within a buffer)
    const unsigned aLm = (unsigned)((wm*64 + (lane & 15))*80 + ((lane >> 4) * 8) * 2);
    const unsigned bLm = (unsigned)((wn*32 + (lane & 7) + ((lane >> 4) << 3))*80
                                    + (((lane >> 3) & 1) * 8) * 2);

    // A loaders: 1024 float4 per chunk, 4 per thread
    const int ar[4] = { tid >> 3, (tid+256) >> 3, (tid+512) >> 3, (tid+768) >> 3 };
    const int as[4] = { tid & 7,  (tid+256) & 7,  (tid+512) & 7,  (tid+768) & 7 };
    // B loaders
    const int br0 = tid >> 2, bs0 = tid & 3;
    const int br1 = (tid + 256) >> 2, bs1 = (tid + 256) & 3;

    float4 rA[4];
    auto loadA = [&](int kc) {
        #pragma unroll
        for (int j = 0; j < 4; ++j)
            rA[j] = *(const float4*)(enc + (size_t)(m0 + ar[j])*KD_ + kc*32 + as[j]*4);
    };
    auto cvtStore = [&](int bf) {
        #pragma unroll
        for (int j = 0; j < 4; ++j) {
            __nv_bfloat16 h0 = __float2bfloat16(rA[j].x), h1 = __float2bfloat16(rA[j].y);
            __nv_bfloat16 h2 = __float2bfloat16(rA[j].z), h3 = __float2bfloat16(rA[j].w);
            __nv_bfloat162 hp0 = __halves2bfloat162(h0, h1), hp1 = __halves2bfloat162(h2, h3);
            __nv_bfloat162 lp0 = __floats2bfloat162_rn(rA[j].x - __bfloat162float(h0),
                                                       rA[j].y - __bfloat162float(h1));
            __nv_bfloat162 lp1 = __floats2bfloat162_rn(rA[j].z - __bfloat162float(h2),
                                                       rA[j].w - __bfloat162float(h3));
            *(uint2*)(sm + OAH_ + bf*10240 + ar[j]*80 + as[j]*8) = make_uint2(*(unsigned*)&hp0, *(unsigned*)&hp1);
            *(uint2*)(sm + OAL_ + bf*10240 + ar[j]*80 + as[j]*8) = make_uint2(*(unsigned*)&lp0, *(unsigned*)&lp1);
        }
    };
    auto issueB = [&](int kc, int bf) {
        cp16(sbase + OBH_ + bf*10240 + br0*80 + bs0*16, g_WcH + (size_t)(n0c + br0)*KD_ + kc*32 + bs0*8);
        cp16(sbase + OBL_ + bf*10240 + br0*80 + bs0*16, g_WcL + (size_t)(n0c + br0)*KD_ + kc*32 + bs0*8);
        cp16(sbase + OBH_ + bf*10240 + br1*80 + bs1*16, g_WcH + (size_t)(n0c + br1)*KD_ + kc*32 + bs1*8);
        cp16(sbase + OBL_ + bf*10240 + br1*80 + bs1*16, g_WcL + (size_t)(n0c + br1)*KD_ + kc*32 + bs1*8);
        CP_COMMIT();
    };

    // prologue: B groups 0,1 in flight; A(0) staged to abuf0; rA holds A(1)
    issueB(0, 0);
    issueB(1, 1);
    loadA(0);
    cvtStore(0);
    loadA(1);

    for (int kc = 0; kc < 16; ++kc) {
        if (kc < 15) { CP_WAIT(1); } else { CP_WAIT(0); }
        __syncthreads();
        // post-barrier: all MMAs on chunk kc-1 complete -> safe to overwrite
        // abuf (kc+1)&1 (== (kc-1)&1) and bbuf (kc+2)%3 (== (kc-1)%3).
        if (kc + 1 <= 15) cvtStore((kc + 1) & 1);      // uses rA = A(kc+1)
        if (kc + 2 <= 15) { loadA(kc + 2); issueB(kc + 2, (kc + 2) % 3); }

        const unsigned ahA = sbase + OAH_ + (kc & 1)*10240 + aLm;
        const unsigned alA = sbase + OAL_ + (kc & 1)*10240 + aLm;
        const unsigned bhA = sbase + OBH_ + (kc % 3)*10240 + bLm;
        const unsigned blA = sbase + OBL_ + (kc % 3)*10240 + bLm;

        #pragma unroll
        for (int kg = 0; kg < 2; ++kg) {
            const unsigned ko = kg*32;   // 16 bf16 = 32 bytes
            unsigned ah[4][4], al[4][4], bh[4][2], bl[4][2];
            #pragma unroll
            for (int mt = 0; mt < 4; ++mt) {
                LDSM4(ah[mt][0], ah[mt][1], ah[mt][2], ah[mt][3], ahA + mt*16*80 + ko);
                LDSM4(al[mt][0], al[mt][1], al[mt][2], al[mt][3], alA + mt*16*80 + ko);
            }
            #pragma unroll
            for (int np = 0; np < 2; ++np) {
                LDSM4(bh[2*np][0], bh[2*np][1], bh[2*np+1][0], bh[2*np+1][1], bhA + np*16*80 + ko);
                LDSM4(bl[2*np][0], bl[2*np][1], bl[2*np+1][0], bl[2*np+1][1], blA + np*16*80 + ko);
            }
            #pragma unroll
            for (int nt = 0; nt < 4; ++nt)
                #pragma unroll
                for (int mt = 0; mt < 4; ++mt) {
                    hmma16816(acc[mt][nt], ah[mt], bh[nt]);
                    hmma16816(acc[mt][nt], ah[mt], bl[nt]);
                    hmma16816(acc[mt][nt], al[mt], bh[nt]);
                }
        }
    }

    __syncthreads();
    // epilogue: partial tanh-dot for this CTA's 128 columns
    const int r = lane >> 2;
    #pragma unroll
    for (int mt = 0; mt < 4; ++mt) {
        float p0 = 0.f, p1 = 0.f;
        #pragma unroll
        for (int nt = 0; nt < 4; ++nt) {
            int n0 = wn*32 + nt*8 + q2;
            float b0 = s_bias[n0],  st0 = s_state[n0];
            float b1 = s_bias[n0+1], st1 = s_state[n0+1];
            p0 += tanhf(acc[mt][nt][0] + b0)*st0 + tanhf(acc[mt][nt][1] + b1)*st1;
            p1 += tanhf(acc[mt][nt][2] + b0)*st0 + tanhf(acc[mt][nt][3] + b1)*st1;
        }
        p0 += __shfl_xor_sync(0xffffffffu, p0, 1);
        p0 += __shfl_xor_sync(0xffffffffu, p0, 2);
        p1 += __shfl_xor_sync(0xffffffffu, p1, 1);
        p1 += __shfl_xor_sync(0xffffffffu, p1, 2);
        if ((lane & 3) == 0) {
            atomicAdd(&s_p[wm*64 + mt*16 + r],     p0);
            atomicAdd(&s_p[wm*64 + mt*16 + r + 8], p1);
        }
    }
    __syncthreads();
    if (tid < 128) atomicAdd(&g_pacc[m0 + tid], s_p[tid]);
}

// ---- softmax pass 1 (stats only) ----
__global__ __launch_bounds__(256) void k_smax1() {
    __shared__ float buf[4096];
    __shared__ float red[8];
    const int b = blockIdx.y, c = blockIdx.x, tid = threadIdx.x;
    const int i0 = c * 4096;

    float mx = -1e30f;
    for (int t = tid; t < 4096; t += 256) {
        int i = i0 + t;
        float v = -1e30f;
        if (i < V_) v = g_score_g[(size_t)b*V_ + i];
        else if (i < TOT_) v = g_score_c[b*S_ + (i - V_)];
        buf[t] = v;
        mx = fmaxf(mx, v);
    }
    #pragma unroll
    for (int o = 16; o; o >>= 1) mx = fmaxf(mx, __shfl_xor_sync(0xffffffffu, mx, o));
    if ((tid & 31) == 0) red[tid >> 5] = mx;
    __syncthreads();
    if (tid < 8) {
        float v = red[tid];
        #pragma unroll
        for (int o = 4; o; o >>= 1) v = fmaxf(v, __shfl_xor_sync(0xffu, v, o));
        red[tid] = v;
    }
    __syncthreads();
    const float ml = red[0];
    __syncthreads();

    float sum = 0.f;
    for (int t = tid; t < 4096; t += 256) {
        int i = i0 + t;
        if (i < TOT_) sum += expf(buf[t] - ml);
    }
    #pragma unroll
    for (int o = 16; o; o >>= 1) sum += __shfl_xor_sync(0xffffffffu, sum, o);
    if ((tid & 31) == 0) red[tid >> 5] = sum;
    __syncthreads();
    if (tid == 0) {
        float s = 0.f;
        #pragma unroll
        for (int w = 0; w < 8; ++w) s += red[w];
        g_pm[b*NCH_ + c] = ml;
        g_ps[b*NCH_ + c] = s;
    }
}

// ---- softmax combine ----
__global__ void k_smax2(float* __restrict__ out) {
    int b = threadIdx.x;
    if (b >= B_) return;
    float m = -1e30f;
    for (int c = 0; c < NCH_; ++c) m = fmaxf(m, g_pm[b*NCH_ + c]);
    float sum = 0.f;
    for (int c = 0; c < NCH_; ++c) sum += g_ps[b*NCH_ + c] * expf(g_pm[b*NCH_ + c] - m);
    g_gm[b] = m;
    g_ginv[b] = 1.f / sum;
    for (int j = 0; j < OOV_; ++j) out[(size_t)b*VEXT_ + V_ + j] = 1e-4f;
}

// ---- write prob_g ----
__global__ __launch_bounds__(256) void k_smax3(float* __restrict__ out) {
    const int b = blockIdx.y, c = blockIdx.x, tid = threadIdx.x;
    const int i0 = c * 4096;
    const float m = g_gm[b], inv = g_ginv[b];
    for (int t = tid; t < 4096; t += 256) {
        int i = i0 + t;
        if (i < V_) out[(size_t)b*VEXT_ + i] = expf(g_score_g[(size_t)b*V_ + i] - m) * inv;
    }
}

// ---- prob_c + rowsums ----
__global__ void k_rowsums(const int* __restrict__ eidx) {
    int gid = blockIdx.x*blockDim.x + threadIdx.x;
    if (gid < M_) {
        int b = gid >> 11;
        float pc = expf(g_score_c[gid] - g_gm[b]) * g_ginv[b];
        g_prob_c[gid] = pc;
        atomicAdd(&g_rowsums[(size_t)b*VEXT_ + eidx[gid]], pc);
    }
}

// ---- final scatter; collect matches ----
__global__ void k_final(const int* __restrict__ eidx, const int* __restrict__ input_idx,
                        float* __restrict__ out)
{
    int gid = blockIdx.x*blockDim.x + threadIdx.x;
    if (gid >= M_) return;
    int b = gid >> 11;
    int idx = eidx[gid];
    float pc = g_prob_c[gid];
    float attn = pc;
    if (g_counts[idx] > 1) attn = pc * g_rowsums[(size_t)b*VEXT_ + idx];
    atomicAdd(&out[(size_t)b*VEXT_ + idx], attn);

    if (idx == input_idx[b]) {
        int rs = g_rs[b];
        float f = (rs > 1) ? (1.f / (float)rs) : 1.f;
        int slot = atomicAdd(&g_mcount, 1);
        if (slot < 8192) { g_mlist[slot] = gid; g_mval[slot] = pc * f; }
    }
}

// ---- weighted_out from sparse match list ----
__global__ __launch_bounds__(512) void k_weighted(const float* __restrict__ enc,
                                                  float* __restrict__ out)
{
    const int d = threadIdx.x;
    const int n = g_mcount < 8192 ? g_mcount : 8192;
    for (int e = 0; e < n; ++e) {
        int gid = g_mlist[e];
        int b = gid >> 11;
        out[OFF_W + b*512 + d] += g_mval[e] * enc[(size_t)gid*KD_ + d];
    }
}

extern "C" void kernel_launch(void* const* d_in, const int* in_sizes, int n_in,
                              void* d_out, int out_size)
{
    const int*   input_idx = (const int*)  d_in[0];
    const float* encoded   = (const float*)d_in[1];
    const int*   eidx      = (const int*)  d_in[2];
    const float* prev_st   = (const float*)d_in[3];
    const float* weighted  = (const float*)d_in[4];
    const float* embed     = (const float*)d_in[6];
    const float* w_ih      = (const float*)d_in[7];
    const float* w_hh      = (const float*)d_in[8];
    const float* b_ih      = (const float*)d_in[9];
    const float* b_hh      = (const float*)d_in[10];
    const float* Wo_w      = (const float*)d_in[11];
    const float* Wo_b      = (const float*)d_in[12];
    const float* Wc_w      = (const float*)d_in[13];
    const float* Wc_b      = (const float*)d_in[14];
    float* out = (float*)d_out;

    cudaFuncSetAttribute(k_score_c, cudaFuncAttributeMaxDynamicSharedMemorySize, SC_SMEM);
    cudaFuncSetAttribute(k_score_g, cudaFuncAttributeMaxDynamicSharedMemorySize, SG_SMEM);

    // k_score_c at launch index 3 (ncu profiling slot)
    k_prep<<<4096, 256>>>(input_idx, embed, weighted, prev_st, Wc_w, out);
    k_gru_gemm<<<dim3(96, 2), 256>>>(w_ih, w_hh);
    k_gates<<<B_, H_>>>(b_ih, b_hh, prev_st, out);
    k_score_c<<<(M_/128)*2, 256, SC_SMEM>>>(encoded, Wc_b);
    k_counts<<<M_/256, 256>>>(eidx, input_idx);
    k_score_g<<<(V_ + 63)/64, 256, SG_SMEM>>>(Wo_w, Wo_b);
    k_smax1<<<dim3(NCH_, B_), 256>>>();
    k_smax2<<<1, 32>>>(out);
    k_smax3<<<dim3(NCH_, B_), 256>>>(out);
    k_rowsums<<<M_/256, 256>>>(eidx);
    k_final<<<M_/256, 256>>>(eidx, input_idx, out);
    k_weighted<<<1, 512>>>(encoded, out);
}

// round 16
// speedup vs baseline: 1.3617x; 1.3617x over previous
#include <cuda_runtime.h>
#include <cuda_bf16.h>
#include <cuda_fp16.h>
#include <math.h>

#define B_    32
#define S_    2048
#define H_    256
#define V_    50000
#define OOV_  12
#define VEXT_ 50012
#define M_    (B_*S_)
#define KD_   512
#define XD_   768
#define TOT_  (V_ + S_)
#define NCH_  13

#define OFF_STATE 1600384
#define OFF_W     1608576

// ---------------- scratch ----------------
__device__ __align__(16) float g_xT[XD_*B_];
__device__ __align__(16) float g_hT[H_*B_];
__device__ __align__(16) float g_gx[768*B_];
__device__ __align__(16) float g_gh[768*B_];
__device__ __align__(16) float g_state[B_*H_];
__device__ __align__(16) float g_score_g[B_*V_];
__device__ __align__(16) float g_score_c[M_];
__device__ __align__(16) float g_pacc[M_];
__device__ __align__(16) float g_prob_c[M_];
__device__            int   g_counts[VEXT_];
__device__            int   g_rs[B_];
__device__ __align__(16) float g_rowsums[B_*VEXT_];
__device__ __align__(16) __half g_WcF[H_*KD_];
__device__ float g_pm[B_*NCH_];
__device__ float g_ps[B_*NCH_];
__device__ float g_gm[B_];
__device__ float g_ginv[B_];
__device__ int   g_mcount;
__device__ int   g_mlist[8192];
__device__ float g_mval[8192];

__device__ __forceinline__ float sigm(float x) { return 1.f / (1.f + expf(-x)); }

__device__ __forceinline__ void hmma16816f(float* c, const unsigned* a, const unsigned* b) {
    asm volatile(
        "mma.sync.aligned.m16n8k16.row.col.f32.f16.f16.f32 "
        "{%0,%1,%2,%3}, {%4,%5,%6,%7}, {%8,%9}, {%0,%1,%2,%3};"
        : "+f"(c[0]), "+f"(c[1]), "+f"(c[2]), "+f"(c[3])
        : "r"(a[0]), "r"(a[1]), "r"(a[2]), "r"(a[3]), "r"(b[0]), "r"(b[1]));
}
__device__ __forceinline__ unsigned smem_u32(const void* p) {
    unsigned a;
    asm("{ .reg .u64 t; cvta.to.shared.u64 t, %1; cvt.u32.u64 %0, t; }" : "=r"(a) : "l"(p));
    return a;
}
__device__ __forceinline__ void cp16(unsigned dst, const void* src) {
    asm volatile("cp.async.cg.shared.global [%0], [%1], 16;"
                 :: "r"(dst), "l"(__cvta_generic_to_global(src)) : "memory");
}
#define CP_COMMIT() asm volatile("cp.async.commit_group;" ::: "memory")
#define CP_WAIT(n)  asm volatile("cp.async.wait_group %0;" :: "n"(n) : "memory")
#define LDSM4(r0, r1, r2, r3, addr) \
    asm volatile("ldmatrix.sync.aligned.m8n8.x4.shared.b16 {%0,%1,%2,%3}, [%4];" \
                 : "=r"(r0), "=r"(r1), "=r"(r2), "=r"(r3) : "r"(addr))

// ---- K0: zero scratch + Wc fp16 convert + gathers ----
__global__ void k_prep(const int* __restrict__ input_idx, const float* __restrict__ embed,
                       const float* __restrict__ weighted, const float* __restrict__ prev_state,
                       const float* __restrict__ Wc_w, float* __restrict__ out)
{
    const int N0 = VEXT_;
    const int N1 = B_*VEXT_;
    const int N2 = H_*KD_;
    const int N3 = XD_*B_;
    const int N4 = H_*B_;
    const int N5 = B_*512;
    const int N6 = B_;
    const int N7 = M_;
    const int total = N0 + N1 + N2 + N3 + N4 + N5 + N6 + N7 + 1;
    for (int gid = blockIdx.x*blockDim.x + threadIdx.x; gid < total; gid += gridDim.x*blockDim.x) {
        int i = gid;
        if (i < N0) { g_counts[i] = 0; continue; }
        i -= N0;
        if (i < N1) { g_rowsums[i] = 0.f; continue; }
        i -= N1;
        if (i < N2) { g_WcF[i] = __float2half(Wc_w[i]); continue; }
        i -= N2;
        if (i < N3) {
            int k = i >> 5; int b = i & 31;
            g_xT[i] = (k < 256) ? embed[(size_t)input_idx[b]*256 + k] : weighted[b*512 + (k-256)];
            continue;
        }
        i -= N3;
        if (i < N4) { int k = i >> 5; int b = i & 31; g_hT[i] = prev_state[b*H_ + k]; continue; }
        i -= N4;
        if (i < N5) { out[OFF_W + i] = 0.f; continue; }
        i -= N5;
        if (i < N6) { g_rs[i] = 0; continue; }
        i -= N6;
        if (i < N7) { g_pacc[i] = 0.f; continue; }
        g_mcount = 0;
    }
}

// ---- histogram + per-row match + FINAL score_c (tanh of cross-CTA partials) ----
__global__ void k_counts(const int* __restrict__ eidx, const int* __restrict__ input_idx) {
    int gid = blockIdx.x*blockDim.x + threadIdx.x;
    if (gid < M_) {
        int idx = eidx[gid];
        atomicAdd(&g_counts[idx], 1);
        int b = gid >> 11;
        if (idx == input_idx[b]) atomicAdd(&g_rs[b], 1);
        float v = tanhf(g_pacc[gid]);
        if (idx == 0) v -= 1000.f;
        g_score_c[gid] = v;
    }
}

// ---- GRU gemms ----
__global__ void k_gru_gemm(const float* __restrict__ w_ih, const float* __restrict__ w_hh) {
    const int tid = threadIdx.x;
    const int b = tid & 31;
    const int j = blockIdx.x*8 + (tid >> 5);
    if (blockIdx.y == 0) {
        const float4* wr = (const float4*)(w_ih + (size_t)j*XD_);
        float acc = 0.f;
        #pragma unroll 8
        for (int k4 = 0; k4 < XD_/4; ++k4) {
            float4 wv = wr[k4];
            int k = k4*4;
            acc += wv.x*g_xT[(k+0)*32+b] + wv.y*g_xT[(k+1)*32+b]
                 + wv.z*g_xT[(k+2)*32+b] + wv.w*g_xT[(k+3)*32+b];
        }
        g_gx[j*32+b] = acc;
    } else {
        const float4* wr = (const float4*)(w_hh + (size_t)j*H_);
        float acc = 0.f;
        #pragma unroll 8
        for (int k4 = 0; k4 < H_/4; ++k4) {
            float4 wv = wr[k4];
            int k = k4*4;
            acc += wv.x*g_hT[(k+0)*32+b] + wv.y*g_hT[(k+1)*32+b]
                 + wv.z*g_hT[(k+2)*32+b] + wv.w*g_hT[(k+3)*32+b];
        }
        g_gh[j*32+b] = acc;
    }
}

// ---- gates ----
__global__ void k_gates(const float* __restrict__ b_ih, const float* __restrict__ b_hh,
                        const float* __restrict__ prev_state, float* __restrict__ out)
{
    const int b = blockIdx.x, h = threadIdx.x;
    float xr = g_gx[h*32+b]        + b_ih[h];
    float xz = g_gx[(256+h)*32+b]  + b_ih[256+h];
    float xn = g_gx[(512+h)*32+b]  + b_ih[512+h];
    float hr = g_gh[h*32+b]        + b_hh[h];
    float hz = g_gh[(256+h)*32+b]  + b_hh[256+h];
    float hn = g_gh[(512+h)*32+b]  + b_hh[512+h];
    float r = sigm(xr + hr);
    float z = sigm(xz + hz);
    float n = tanhf(xn + r*hn);
    float st = (1.f - z)*n + z*prev_state[b*H_+h];
    g_state[b*H_+h] = st;
    out[OFF_STATE + b*H_ + h] = st;
}

// ---- score_g: smem-staged coalesced W ----
__global__ __launch_bounds__(256) void k_score_g(const float* __restrict__ Wo_w,
                                                 const float* __restrict__ Wo_b)
{
    extern __shared__ __align__(16) float sg[];
    float* st = sg;                       // [256k][32b]
    float4* sw4 = (float4*)(sg + 8192);   // [64v][64 float4]
    const int tid = threadIdx.x;
    const int v0 = blockIdx.x * 64;

    for (int i = tid; i < 8192; i += 256) {
        int k = i >> 5, b = i & 31;
        st[i] = g_state[b*H_ + k];
    }
    for (int i = tid; i < 4096; i += 256) {
        int row = i >> 6, seg = i & 63;
        int v = v0 + row;
        sw4[i] = (v < V_) ? ((const float4*)(Wo_w + (size_t)v*H_))[seg]
                          : make_float4(0.f, 0.f, 0.f, 0.f);
    }
    __syncthreads();

    const int w = tid >> 5;
    const int lane = tid & 31;
    if (v0 + w*8 >= V_) return;

    float a[8];
    #pragma unroll
    for (int r = 0; r < 8; ++r) a[r] = 0.f;

    #pragma unroll 4
    for (int k4 = 0; k4 < 64; ++k4) {
        float s0 = st[(k4*4+0)*32 + lane];
        float s1 = st[(k4*4+1)*32 + lane];
        float s2 = st[(k4*4+2)*32 + lane];
        float s3 = st[(k4*4+3)*32 + lane];
        #pragma unroll
        for (int r = 0; r < 8; ++r) {
            float4 wv = sw4[(w*8+r)*64 + k4];
            a[r] += wv.x*s0 + wv.y*s1 + wv.z*s2 + wv.w*s3;
        }
    }
    int vb = v0 + w*8;
    float4 o0, o1;
    o0.x = a[0] + Wo_b[vb+0]; o0.y = a[1] + Wo_b[vb+1];
    o0.z = a[2] + Wo_b[vb+2]; o0.w = a[3] + Wo_b[vb+3];
    o1.x = a[4] + Wo_b[vb+4]; o1.y = a[5] + Wo_b[vb+5];
    o1.z = a[6] + Wo_b[vb+6]; o1.w = a[7] + Wo_b[vb+7];
    *(float4*)(g_score_g + (size_t)lane*V_ + vb)     = o0;
    *(float4*)(g_score_g + (size_t)lane*V_ + vb + 4) = o1;
}
#define SG_SMEM 98304

// ---- K4: single-pass fp16 HMMA score_c partials (2 CTA/SM, ldmatrix, 1-barrier pipe) ----
// CTA 128(m) x 128(n), K=512 in 16 chunks of 32. 256 threads, 8 warps = 2(m)x4(n),
// warp tile 64x32. A double-buffered fp16, B triple-buffered cp.async fp16.
#define OA_  0        // 2 bufs x 10240
#define OB_  20480    // 3 bufs x 10240
#define OST_ 51200
#define OBI_ 51712
#define OP_  52224
#define SC_SMEM 52736

__global__ __launch_bounds__(256, 2) void k_score_c(const float* __restrict__ enc,
                                                    const float* __restrict__ wcb)
{
    extern __shared__ __align__(16) char sm[];
    const unsigned sbase = smem_u32(sm);
    const int tid = threadIdx.x;
    const int lane = tid & 31;
    const int wid = tid >> 5;
    const int wm = wid >> 2;          // 0..1 : rows wm*64
    const int wn = wid & 3;           // 0..3 : cols wn*32
    const int q2 = (lane & 3) * 2;
    const int m0  = (blockIdx.x >> 1) * 128;
    const int n0c = (blockIdx.x & 1) * 128;
    const int b   = m0 >> 11;

    float* s_state = (float*)(sm + OST_);
    float* s_bias  = (float*)(sm + OBI_);
    float* s_p     = (float*)(sm + OP_);
    if (tid < 128) {
        s_state[tid] = g_state[b*H_ + n0c + tid];
        s_bias[tid]  = wcb[n0c + tid];
        s_p[tid] = 0.f;
    }

    float acc[4][4][4];
    #pragma unroll
    for (int mt = 0; mt < 4; ++mt)
        #pragma unroll
        for (int nt = 0; nt < 4; ++nt)
            #pragma unroll
            for (int e = 0; e < 4; ++e) acc[mt][nt][e] = 0.f;

    // ldmatrix lane address offsets (bytes within a buffer)
    const unsigned aLm = (unsigned)((wm*64 + (lane & 15))*80 + ((lane >> 4) * 8) * 2);
    const unsigned bLm = (unsigned)((wn*32 + (lane & 7) + ((lane >> 4) << 3))*80
                                    + (((lane >> 3) & 1) * 8) * 2);

    // A loaders: 1024 float4 per chunk, 4 per thread
    const int ar[4] = { tid >> 3, (tid+256) >> 3, (tid+512) >> 3, (tid+768) >> 3 };
    const int as[4] = { tid & 7,  (tid+256) & 7,  (tid+512) & 7,  (tid+768) & 7 };
    // B loader: 512 cp16 per chunk, 2 per thread
    const int br0 = tid >> 2, bs0 = tid & 3;
    const int br1 = (tid + 256) >> 2, bs1 = (tid + 256) & 3;

    float4 rA[4];
    auto loadA = [&](int kc) {
        #pragma unroll
        for (int j = 0; j < 4; ++j)
            rA[j] = *(const float4*)(enc + (size_t)(m0 + ar[j])*KD_ + kc*32 + as[j]*4);
    };
    auto cvtStore = [&](int bf) {
        #pragma unroll
        for (int j = 0; j < 4; ++j) {
            __half2 p0 = __floats2half2_rn(rA[j].x, rA[j].y);
            __half2 p1 = __floats2half2_rn(rA[j].z, rA[j].w);
            *(uint2*)(sm + OA_ + bf*10240 + ar[j]*80 + as[j]*8) =
                make_uint2(*(unsigned*)&p0, *(unsigned*)&p1);
        }
    };
    auto issueB = [&](int kc, int bf) {
        cp16(sbase + OB_ + bf*10240 + br0*80 + bs0*16, g_WcF + (size_t)(n0c + br0)*KD_ + kc*32 + bs0*8);
        cp16(sbase + OB_ + bf*10240 + br1*80 + bs1*16, g_WcF + (size_t)(n0c + br1)*KD_ + kc*32 + bs1*8);
        CP_COMMIT();
    };

    // prologue: B groups 0,1 in flight; A(0) staged to abuf0; rA holds A(1)
    issueB(0, 0);
    issueB(1, 1);
    loadA(0);
    cvtStore(0);
    loadA(1);

    for (int kc = 0; kc < 16; ++kc) {
        if (kc < 15) { CP_WAIT(1); } else { CP_WAIT(0); }
        __syncthreads();
        // post-barrier: all MMAs on chunk kc-1 complete -> safe to overwrite
        // abuf (kc+1)&1 (== (kc-1)&1) and bbuf (kc+2)%3 (== (kc-1)%3).
        if (kc + 1 <= 15) cvtStore((kc + 1) & 1);      // uses rA = A(kc+1)
        if (kc + 2 <= 15) { loadA(kc + 2); issueB(kc + 2, (kc + 2) % 3); }

        const unsigned ahA = sbase + OA_ + (kc & 1)*10240 + aLm;
        const unsigned bhA = sbase + OB_ + (kc % 3)*10240 + bLm;

        #pragma unroll
        for (int kg = 0; kg < 2; ++kg) {
            const unsigned ko = kg*32;   // 16 fp16 = 32 bytes
            unsigned ah[4][4], bh[4][2];
            #pragma unroll
            for (int mt = 0; mt < 4; ++mt)
                LDSM4(ah[mt][0], ah[mt][1], ah[mt][2], ah[mt][3], ahA + mt*16*80 + ko);
            #pragma unroll
            for (int np = 0; np < 2; ++np)
                LDSM4(bh[2*np][0], bh[2*np][1], bh[2*np+1][0], bh[2*np+1][1], bhA + np*16*80 + ko);
            #pragma unroll
            for (int nt = 0; nt < 4; ++nt)
                #pragma unroll
                for (int mt = 0; mt < 4; ++mt)
                    hmma16816f(acc[mt][nt], ah[mt], bh[nt]);
        }
    }

    __syncthreads();
    // epilogue: partial tanh-dot for this CTA's 128 columns
    const int r = lane >> 2;
    #pragma unroll
    for (int mt = 0; mt < 4; ++mt) {
        float p0 = 0.f, p1 = 0.f;
        #pragma unroll
        for (int nt = 0; nt < 4; ++nt) {
            int n0 = wn*32 + nt*8 + q2;
            float b0 = s_bias[n0],  st0 = s_state[n0];
            float b1 = s_bias[n0+1], st1 = s_state[n0+1];
            p0 += tanhf(acc[mt][nt][0] + b0)*st0 + tanhf(acc[mt][nt][1] + b1)*st1;
            p1 += tanhf(acc[mt][nt][2] + b0)*st0 + tanhf(acc[mt][nt][3] + b1)*st1;
        }
        p0 += __shfl_xor_sync(0xffffffffu, p0, 1);
        p0 += __shfl_xor_sync(0xffffffffu, p0, 2);
        p1 += __shfl_xor_sync(0xffffffffu, p1, 1);
        p1 += __shfl_xor_sync(0xffffffffu, p1, 2);
        if ((lane & 3) == 0) {
            atomicAdd(&s_p[wm*64 + mt*16 + r],     p0);
            atomicAdd(&s_p[wm*64 + mt*16 + r + 8], p1);
        }
    }
    __syncthreads();
    if (tid < 128) atomicAdd(&g_pacc[m0 + tid], s_p[tid]);
}

// ---- softmax pass 1 (stats only) ----
__global__ __launch_bounds__(256) void k_smax1() {
    __shared__ float buf[4096];
    __shared__ float red[8];
    const int b = blockIdx.y, c = blockIdx.x, tid = threadIdx.x;
    const int i0 = c * 4096;

    float mx = -1e30f;
    for (int t = tid; t < 4096; t += 256) {
        int i = i0 + t;
        float v = -1e30f;
        if (i < V_) v = g_score_g[(size_t)b*V_ + i];
        else if (i < TOT_) v = g_score_c[b*S_ + (i - V_)];
        buf[t] = v;
        mx = fmaxf(mx, v);
    }
    #pragma unroll
    for (int o = 16; o; o >>= 1) mx = fmaxf(mx, __shfl_xor_sync(0xffffffffu, mx, o));
    if ((tid & 31) == 0) red[tid >> 5] = mx;
    __syncthreads();
    if (tid < 8) {
        float v = red[tid];
        #pragma unroll
        for (int o = 4; o; o >>= 1) v = fmaxf(v, __shfl_xor_sync(0xffu, v, o));
        red[tid] = v;
    }
    __syncthreads();
    const float ml = red[0];
    __syncthreads();

    float sum = 0.f;
    for (int t = tid; t < 4096; t += 256) {
        int i = i0 + t;
        if (i < TOT_) sum += expf(buf[t] - ml);
    }
    #pragma unroll
    for (int o = 16; o; o >>= 1) sum += __shfl_xor_sync(0xffffffffu, sum, o);
    if ((tid & 31) == 0) red[tid >> 5] = sum;
    __syncthreads();
    if (tid == 0) {
        float s = 0.f;
        #pragma unroll
        for (int w = 0; w < 8; ++w) s += red[w];
        g_pm[b*NCH_ + c] = ml;
        g_ps[b*NCH_ + c] = s;
    }
}

// ---- softmax combine ----
__global__ void k_smax2(float* __restrict__ out) {
    int b = threadIdx.x;
    if (b >= B_) return;
    float m = -1e30f;
    for (int c = 0; c < NCH_; ++c) m = fmaxf(m, g_pm[b*NCH_ + c]);
    float sum = 0.f;
    for (int c = 0; c < NCH_; ++c) sum += g_ps[b*NCH_ + c] * expf(g_pm[b*NCH_ + c] - m);
    g_gm[b] = m;
    g_ginv[b] = 1.f / sum;
    for (int j = 0; j < OOV_; ++j) out[(size_t)b*VEXT_ + V_ + j] = 1e-4f;
}

// ---- write prob_g ----
__global__ __launch_bounds__(256) void k_smax3(float* __restrict__ out) {
    const int b = blockIdx.y, c = blockIdx.x, tid = threadIdx.x;
    const int i0 = c * 4096;
    const float m = g_gm[b], inv = g_ginv[b];
    for (int t = tid; t < 4096; t += 256) {
        int i = i0 + t;
        if (i < V_) out[(size_t)b*VEXT_ + i] = expf(g_score_g[(size_t)b*V_ + i] - m) * inv;
    }
}

// ---- prob_c + rowsums ----
__global__ void k_rowsums(const int* __restrict__ eidx) {
    int gid = blockIdx.x*blockDim.x + threadIdx.x;
    if (gid < M_) {
        int b = gid >> 11;
        float pc = expf(g_score_c[gid] - g_gm[b]) * g_ginv[b];
        g_prob_c[gid] = pc;
        atomicAdd(&g_rowsums[(size_t)b*VEXT_ + eidx[gid]], pc);
    }
}

// ---- final scatter; collect matches ----
__global__ void k_final(const int* __restrict__ eidx, const int* __restrict__ input_idx,
                        float* __restrict__ out)
{
    int gid = blockIdx.x*blockDim.x + threadIdx.x;
    if (gid >= M_) return;
    int b = gid >> 11;
    int idx = eidx[gid];
    float pc = g_prob_c[gid];
    float attn = pc;
    if (g_counts[idx] > 1) attn = pc * g_rowsums[(size_t)b*VEXT_ + idx];
    atomicAdd(&out[(size_t)b*VEXT_ + idx], attn);

    if (idx == input_idx[b]) {
        int rs = g_rs[b];
        float f = (rs > 1) ? (1.f / (float)rs) : 1.f;
        int slot = atomicAdd(&g_mcount, 1);
        if (slot < 8192) { g_mlist[slot] = gid; g_mval[slot] = pc * f; }
    }
}

// ---- weighted_out from sparse match list ----
__global__ __launch_bounds__(512) void k_weighted(const float* __restrict__ enc,
                                                  float* __restrict__ out)
{
    const int d = threadIdx.x;
    const int n = g_mcount < 8192 ? g_mcount : 8192;
    for (int e = 0; e < n; ++e) {
        int gid = g_mlist[e];
        int b = gid >> 11;
        out[OFF_W + b*512 + d] += g_mval[e] * enc[(size_t)gid*KD_ + d];
    }
}

extern "C" void kernel_launch(void* const* d_in, const int* in_sizes, int n_in,
                              void* d_out, int out_size)
{
    const int*   input_idx = (const int*)  d_in[0];
    const float* encoded   = (const float*)d_in[1];
    const int*   eidx      = (const int*)  d_in[2];
    const float* prev_st   = (const float*)d_in[3];
    const float* weighted  = (const float*)d_in[4];
    const float* embed     = (const float*)d_in[6];
    const float* w_ih      = (const float*)d_in[7];
    const float* w_hh      = (const float*)d_in[8];
    const float* b_ih      = (const float*)d_in[9];
    const float* b_hh      = (const float*)d_in[10];
    const float* Wo_w      = (const float*)d_in[11];
    const float* Wo_b      = (const float*)d_in[12];
    const float* Wc_w      = (const float*)d_in[13];
    const float* Wc_b      = (const float*)d_in[14];
    float* out = (float*)d_out;

    cudaFuncSetAttribute(k_score_c, cudaFuncAttributeMaxDynamicSharedMemorySize, SC_SMEM);
    cudaFuncSetAttribute(k_score_g, cudaFuncAttributeMaxDynamicSharedMemorySize, SG_SMEM);

    // k_score_c at launch index 3 (ncu profiling slot)
    k_prep<<<4096, 256>>>(input_idx, embed, weighted, prev_st, Wc_w, out);
    k_gru_gemm<<<dim3(96, 2), 256>>>(w_ih, w_hh);
    k_gates<<<B_, H_>>>(b_ih, b_hh, prev_st, out);
    k_score_c<<<(M_/128)*2, 256, SC_SMEM>>>(encoded, Wc_b);
    k_counts<<<M_/256, 256>>>(eidx, input_idx);
    k_score_g<<<(V_ + 63)/64, 256, SG_SMEM>>>(Wo_w, Wo_b);
    k_smax1<<<dim3(NCH_, B_), 256>>>();
    k_smax2<<<1, 32>>>(out);
    k_smax3<<<dim3(NCH_, B_), 256>>>(out);
    k_rowsums<<<M_/256, 256>>>(eidx);
    k_final<<<M_/256, 256>>>(eidx, input_idx, out);
    k_weighted<<<1, 512>>>(encoded, out);
}

// round 17
// speedup vs baseline: 1.3619x; 1.0001x over previous
#include <cuda_runtime.h>
#include <cuda_bf16.h>
#include <cuda_fp16.h>
#include <math.h>

#define B_    32
#define S_    2048
#define H_    256
#define V_    50000
#define OOV_  12
#define VEXT_ 50012
#define M_    (B_*S_)
#define KD_   512
#define XD_   768
#define TOT_  (V_ + S_)
#define NCH_  13

#define OFF_STATE 1600384
#define OFF_W     1608576

// ---------------- scratch ----------------
__device__ __align__(16) float g_xT[XD_*B_];
__device__ __align__(16) float g_hT[H_*B_];
__device__ __align__(16) float g_gx[768*B_];
__device__ __align__(16) float g_gh[768*B_];
__device__ __align__(16) float g_state[B_*H_];
__device__ __align__(16) float g_score_g[B_*V_];
__device__ __align__(16) float g_score_c[M_];
__device__ __align__(16) float g_pacc[M_];
__device__ __align__(16) float g_prob_c[M_];
__device__            int   g_counts[VEXT_];
__device__            int   g_rs[B_];
__device__ __align__(16) float g_rowsums[B_*VEXT_];
__device__ __align__(16) __half g_WcF[H_*KD_];
__device__ float g_pm[B_*NCH_];
__device__ float g_ps[B_*NCH_];
__device__ float g_gm[B_];
__device__ float g_ginv[B_];
__device__ int   g_mcount;
__device__ int   g_mlist[8192];
__device__ float g_mval[8192];

__device__ __forceinline__ float sigm(float x) { return 1.f / (1.f + expf(-x)); }

__device__ __forceinline__ void hmma16816f(float* c, const unsigned* a, const unsigned* b) {
    asm volatile(
        "mma.sync.aligned.m16n8k16.row.col.f32.f16.f16.f32 "
        "{%0,%1,%2,%3}, {%4,%5,%6,%7}, {%8,%9}, {%0,%1,%2,%3};"
        : "+f"(c[0]), "+f"(c[1]), "+f"(c[2]), "+f"(c[3])
        : "r"(a[0]), "r"(a[1]), "r"(a[2]), "r"(a[3]), "r"(b[0]), "r"(b[1]));
}
__device__ __forceinline__ unsigned smem_u32(const void* p) {
    unsigned a;
    asm("{ .reg .u64 t; cvta.to.shared.u64 t, %1; cvt.u32.u64 %0, t; }" : "=r"(a) : "l"(p));
    return a;
}
__device__ __forceinline__ void cp16(unsigned dst, const void* src) {
    asm volatile("cp.async.cg.shared.global [%0], [%1], 16;"
                 :: "r"(dst), "l"(__cvta_generic_to_global(src)) : "memory");
}
#define CP_COMMIT() asm volatile("cp.async.commit_group;" ::: "memory")
#define CP_WAIT(n)  asm volatile("cp.async.wait_group %0;" :: "n"(n) : "memory")
#define LDSM4(r0, r1, r2, r3, addr) \
    asm volatile("ldmatrix.sync.aligned.m8n8.x4.shared.b16 {%0,%1,%2,%3}, [%4];" \
                 : "=r"(r0), "=r"(r1), "=r"(r2), "=r"(r3) : "r"(addr))

// ---- K0: zero scratch + Wc fp16 convert + gathers ----
__global__ void k_prep(const int* __restrict__ input_idx, const float* __restrict__ embed,
                       const float* __restrict__ weighted, const float* __restrict__ prev_state,
                       const float* __restrict__ Wc_w, float* __restrict__ out)
{
    const int N0 = VEXT_;
    const int N1 = B_*VEXT_;
    const int N2 = H_*KD_;
    const int N3 = XD_*B_;
    const int N4 = H_*B_;
    const int N5 = B_*512;
    const int N6 = B_;
    const int N7 = M_;
    const int total = N0 + N1 + N2 + N3 + N4 + N5 + N6 + N7 + 1;
    for (int gid = blockIdx.x*blockDim.x + threadIdx.x; gid < total; gid += gridDim.x*blockDim.x) {
        int i = gid;
        if (i < N0) { g_counts[i] = 0; continue; }
        i -= N0;
        if (i < N1) { g_rowsums[i] = 0.f; continue; }
        i -= N1;
        if (i < N2) { g_WcF[i] = __float2half(Wc_w[i]); continue; }
        i -= N2;
        if (i < N3) {
            int k = i >> 5; int b = i & 31;
            g_xT[i] = (k < 256) ? embed[(size_t)input_idx[b]*256 + k] : weighted[b*512 + (k-256)];
            continue;
        }
        i -= N3;
        if (i < N4) { int k = i >> 5; int b = i & 31; g_hT[i] = prev_state[b*H_ + k]; continue; }
        i -= N4;
        if (i < N5) { out[OFF_W + i] = 0.f; continue; }
        i -= N5;
        if (i < N6) { g_rs[i] = 0; continue; }
        i -= N6;
        if (i < N7) { g_pacc[i] = 0.f; continue; }
        g_mcount = 0;
    }
}

// ---- histogram + per-row match + FINAL score_c (tanh of cross-CTA partials) ----
__global__ void k_counts(const int* __restrict__ eidx, const int* __restrict__ input_idx) {
    int gid = blockIdx.x*blockDim.x + threadIdx.x;
    if (gid < M_) {
        int idx = eidx[gid];
        atomicAdd(&g_counts[idx], 1);
        int b = gid >> 11;
        if (idx == input_idx[b]) atomicAdd(&g_rs[b], 1);
        float v = tanhf(g_pacc[gid]);
        if (idx == 0) v -= 1000.f;
        g_score_c[gid] = v;
    }
}

// ---- GRU gemms ----
__global__ void k_gru_gemm(const float* __restrict__ w_ih, const float* __restrict__ w_hh) {
    const int tid = threadIdx.x;
    const int b = tid & 31;
    const int j = blockIdx.x*8 + (tid >> 5);
    if (blockIdx.y == 0) {
        const float4* wr = (const float4*)(w_ih + (size_t)j*XD_);
        float acc = 0.f;
        #pragma unroll 8
        for (int k4 = 0; k4 < XD_/4; ++k4) {
            float4 wv = wr[k4];
            int k = k4*4;
            acc += wv.x*g_xT[(k+0)*32+b] + wv.y*g_xT[(k+1)*32+b]
                 + wv.z*g_xT[(k+2)*32+b] + wv.w*g_xT[(k+3)*32+b];
        }
        g_gx[j*32+b] = acc;
    } else {
        const float4* wr = (const float4*)(w_hh + (size_t)j*H_);
        float acc = 0.f;
        #pragma unroll 8
        for (int k4 = 0; k4 < H_/4; ++k4) {
            float4 wv = wr[k4];
            int k = k4*4;
            acc += wv.x*g_hT[(k+0)*32+b] + wv.y*g_hT[(k+1)*32+b]
                 + wv.z*g_hT[(k+2)*32+b] + wv.w*g_hT[(k+3)*32+b];
        }
        g_gh[j*32+b] = acc;
    }
}

// ---- gates ----
__global__ void k_gates(const float* __restrict__ b_ih, const float* __restrict__ b_hh,
                        const float* __restrict__ prev_state, float* __restrict__ out)
{
    const int b = blockIdx.x, h = threadIdx.x;
    float xr = g_gx[h*32+b]        + b_ih[h];
    float xz = g_gx[(256+h)*32+b]  + b_ih[256+h];
    float xn = g_gx[(512+h)*32+b]  + b_ih[512+h];
    float hr = g_gh[h*32+b]        + b_hh[h];
    float hz = g_gh[(256+h)*32+b]  + b_hh[256+h];
    float hn = g_gh[(512+h)*32+b]  + b_hh[512+h];
    float r = sigm(xr + hr);
    float z = sigm(xz + hz);
    float n = tanhf(xn + r*hn);
    float st = (1.f - z)*n + z*prev_state[b*H_+h];
    g_state[b*H_+h] = st;
    out[OFF_STATE + b*H_ + h] = st;
}

// ---- score_g: smem-staged coalesced W ----
__global__ __launch_bounds__(256) void k_score_g(const float* __restrict__ Wo_w,
                                                 const float* __restrict__ Wo_b)
{
    extern __shared__ __align__(16) float sg[];
    float* st = sg;                       // [256k][32b]
    float4* sw4 = (float4*)(sg + 8192);   // [64v][64 float4]
    const int tid = threadIdx.x;
    const int v0 = blockIdx.x * 64;

    for (int i = tid; i < 8192; i += 256) {
        int k = i >> 5, b = i & 31;
        st[i] = g_state[b*H_ + k];
    }
    for (int i = tid; i < 4096; i += 256) {
        int row = i >> 6, seg = i & 63;
        int v = v0 + row;
        sw4[i] = (v < V_) ? ((const float4*)(Wo_w + (size_t)v*H_))[seg]
                          : make_float4(0.f, 0.f, 0.f, 0.f);
    }
    __syncthreads();

    const int w = tid >> 5;
    const int lane = tid & 31;
    if (v0 + w*8 >= V_) return;

    float a[8];
    #pragma unroll
    for (int r = 0; r < 8; ++r) a[r] = 0.f;

    #pragma unroll 4
    for (int k4 = 0; k4 < 64; ++k4) {
        float s0 = st[(k4*4+0)*32 + lane];
        float s1 = st[(k4*4+1)*32 + lane];
        float s2 = st[(k4*4+2)*32 + lane];
        float s3 = st[(k4*4+3)*32 + lane];
        #pragma unroll
        for (int r = 0; r < 8; ++r) {
            float4 wv = sw4[(w*8+r)*64 + k4];
            a[r] += wv.x*s0 + wv.y*s1 + wv.z*s2 + wv.w*s3;
        }
    }
    int vb = v0 + w*8;
    float4 o0, o1;
    o0.x = a[0] + Wo_b[vb+0]; o0.y = a[1] + Wo_b[vb+1];
    o0.z = a[2] + Wo_b[vb+2]; o0.w = a[3] + Wo_b[vb+3];
    o1.x = a[4] + Wo_b[vb+4]; o1.y = a[5] + Wo_b[vb+5];
    o1.z = a[6] + Wo_b[vb+6]; o1.w = a[7] + Wo_b[vb+7];
    *(float4*)(g_score_g + (size_t)lane*V_ + vb)     = o0;
    *(float4*)(g_score_g + (size_t)lane*V_ + vb + 4) = o1;
}
#define SG_SMEM 98304

// ---- K4: single-pass fp16 HMMA score_c partials (2 CTA/SM, ldmatrix, 1-barrier pipe) ----
// CTA 128(m) x 128(n), K=512 in 16 chunks of 32. 256 threads, 8 warps = 2(m)x4(n),
// warp tile 64x32. A double-buffered fp16, B triple-buffered cp.async fp16.
#define OA_  0        // 2 bufs x 10240
#define OB_  20480    // 3 bufs x 10240
#define OST_ 51200
#define OBI_ 51712
#define OP_  52224
#define SC_SMEM 52736

__global__ __launch_bounds__(256, 2) void k_score_c(const float* __restrict__ enc,
                                                    const float* __restrict__ wcb)
{
    extern __shared__ __align__(16) char sm[];
    const unsigned sbase = smem_u32(sm);
    const int tid = threadIdx.x;
    const int lane = tid & 31;
    const int wid = tid >> 5;
    const int wm = wid >> 2;          // 0..1 : rows wm*64
    const int wn = wid & 3;           // 0..3 : cols wn*32
    const int q2 = (lane & 3) * 2;
    const int m0  = (blockIdx.x >> 1) * 128;
    const int n0c = (blockIdx.x & 1) * 128;
    const int b   = m0 >> 11;

    float* s_state = (float*)(sm + OST_);
    float* s_bias  = (float*)(sm + OBI_);
    float* s_p     = (float*)(sm + OP_);
    if (tid < 128) {
        s_state[tid] = g_state[b*H_ + n0c + tid];
        s_bias[tid]  = wcb[n0c + tid];
        s_p[tid] = 0.f;
    }

    float acc[4][4][4];
    #pragma unroll
    for (int mt = 0; mt < 4; ++mt)
        #pragma unroll
        for (int nt = 0; nt < 4; ++nt)
            #pragma unroll
            for (int e = 0; e < 4; ++e) acc[mt][nt][e] = 0.f;

    // ldmatrix lane address offsets (bytes within a buffer)
    const unsigned aLm = (unsigned)((wm*64 + (lane & 15))*80 + ((lane >> 4) * 8) * 2);
    const unsigned bLm = (unsigned)((wn*32 + (lane & 7) + ((lane >> 4) << 3))*80
                                    + (((lane >> 3) & 1) * 8) * 2);

    // A loaders: 1024 float4 per chunk, 4 per thread
    const int ar[4] = { tid >> 3, (tid+256) >> 3, (tid+512) >> 3, (tid+768) >> 3 };
    const int as[4] = { tid & 7,  (tid+256) & 7,  (tid+512) & 7,  (tid+768) & 7 };
    // B loader: 512 cp16 per chunk, 2 per thread
    const int br0 = tid >> 2, bs0 = tid & 3;
    const int br1 = (tid + 256) >> 2, bs1 = (tid + 256) & 3;

    float4 rA[4];
    auto loadA = [&](int kc) {
        #pragma unroll
        for (int j = 0; j < 4; ++j)
            rA[j] = *(const float4*)(enc + (size_t)(m0 + ar[j])*KD_ + kc*32 + as[j]*4);
    };
    auto cvtStore = [&](int bf) {
        #pragma unroll
        for (int j = 0; j < 4; ++j) {
            __half2 p0 = __floats2half2_rn(rA[j].x, rA[j].y);
            __half2 p1 = __floats2half2_rn(rA[j].z, rA[j].w);
            *(uint2*)(sm + OA_ + bf*10240 + ar[j]*80 + as[j]*8) =
                make_uint2(*(unsigned*)&p0, *(unsigned*)&p1);
        }
    };
    auto issueB = [&](int kc, int bf) {
        cp16(sbase + OB_ + bf*10240 + br0*80 + bs0*16, g_WcF + (size_t)(n0c + br0)*KD_ + kc*32 + bs0*8);
        cp16(sbase + OB_ + bf*10240 + br1*80 + bs1*16, g_WcF + (size_t)(n0c + br1)*KD_ + kc*32 + bs1*8);
        CP_COMMIT();
    };

    // prologue: B groups 0,1 in flight; A(0) staged to abuf0; rA holds A(1)
    issueB(0, 0);
    issueB(1, 1);
    loadA(0);
    cvtStore(0);
    loadA(1);

    for (int kc = 0; kc < 16; ++kc) {
        if (kc < 15) { CP_WAIT(1); } else { CP_WAIT(0); }
        __syncthreads();
        // post-barrier: all MMAs on chunk kc-1 complete -> safe to overwrite
        // abuf (kc+1)&1 (== (kc-1)&1) and bbuf (kc+2)%3 (== (kc-1)%3).
        if (kc + 1 <= 15) cvtStore((kc + 1) & 1);      // uses rA = A(kc+1)
        if (kc + 2 <= 15) { loadA(kc + 2); issueB(kc + 2, (kc + 2) % 3); }

        const unsigned ahA = sbase + OA_ + (kc & 1)*10240 + aLm;
        const unsigned bhA = sbase + OB_ + (kc % 3)*10240 + bLm;

        #pragma unroll
        for (int kg = 0; kg < 2; ++kg) {
            const unsigned ko = kg*32;   // 16 fp16 = 32 bytes
            unsigned ah[4][4], bh[4][2];
            #pragma unroll
            for (int mt = 0; mt < 4; ++mt)
                LDSM4(ah[mt][0], ah[mt][1], ah[mt][2], ah[mt][3], ahA + mt*16*80 + ko);
            #pragma unroll
            for (int np = 0; np < 2; ++np)
                LDSM4(bh[2*np][0], bh[2*np][1], bh[2*np+1][0], bh[2*np+1][1], bhA + np*16*80 + ko);
            #pragma unroll
            for (int nt = 0; nt < 4; ++nt)
                #pragma unroll
                for (int mt = 0; mt < 4; ++mt)
                    hmma16816f(acc[mt][nt], ah[mt], bh[nt]);
        }
    }

    __syncthreads();
    // epilogue: partial tanh-dot for this CTA's 128 columns
    const int r = lane >> 2;
    #pragma unroll
    for (int mt = 0; mt < 4; ++mt) {
        float p0 = 0.f, p1 = 0.f;
        #pragma unroll
        for (int nt = 0; nt < 4; ++nt) {
            int n0 = wn*32 + nt*8 + q2;
            float b0 = s_bias[n0],  st0 = s_state[n0];
            float b1 = s_bias[n0+1], st1 = s_state[n0+1];
            p0 += tanhf(acc[mt][nt][0] + b0)*st0 + tanhf(acc[mt][nt][1] + b1)*st1;
            p1 += tanhf(acc[mt][nt][2] + b0)*st0 + tanhf(acc[mt][nt][3] + b1)*st1;
        }
        p0 += __shfl_xor_sync(0xffffffffu, p0, 1);
        p0 += __shfl_xor_sync(0xffffffffu, p0, 2);
        p1 += __shfl_xor_sync(0xffffffffu, p1, 1);
        p1 += __shfl_xor_sync(0xffffffffu, p1, 2);
        if ((lane & 3) == 0) {
            atomicAdd(&s_p[wm*64 + mt*16 + r],     p0);
            atomicAdd(&s_p[wm*64 + mt*16 + r + 8], p1);
        }
    }
    __syncthreads();
    if (tid < 128) atomicAdd(&g_pacc[m0 + tid], s_p[tid]);
}

// ---- softmax pass 1 (stats only) ----
__global__ __launch_bounds__(256) void k_smax1() {
    __shared__ float buf[4096];
    __shared__ float red[8];
    const int b = blockIdx.y, c = blockIdx.x, tid = threadIdx.x;
    const int i0 = c * 4096;

    float mx = -1e30f;
    for (int t = tid; t < 4096; t += 256) {
        int i = i0 + t;
        float v = -1e30f;
        if (i < V_) v = g_score_g[(size_t)b*V_ + i];
        else if (i < TOT_) v = g_score_c[b*S_ + (i - V_)];
        buf[t] = v;
        mx = fmaxf(mx, v);
    }
    #pragma unroll
    for (int o = 16; o; o >>= 1) mx = fmaxf(mx, __shfl_xor_sync(0xffffffffu, mx, o));
    if ((tid & 31) == 0) red[tid >> 5] = mx;
    __syncthreads();
    if (tid < 8) {
        float v = red[tid];
        #pragma unroll
        for (int o = 4; o; o >>= 1) v = fmaxf(v, __shfl_xor_sync(0xffu, v, o));
        red[tid] = v;
    }
    __syncthreads();
    const float ml = red[0];
    __syncthreads();

    float sum = 0.f;
    for (int t = tid; t < 4096; t += 256) {
        int i = i0 + t;
        if (i < TOT_) sum += expf(buf[t] - ml);
    }
    #pragma unroll
    for (int o = 16; o; o >>= 1) sum += __shfl_xor_sync(0xffffffffu, sum, o);
    if ((tid & 31) == 0) red[tid >> 5] = sum;
    __syncthreads();
    if (tid == 0) {
        float s = 0.f;
        #pragma unroll
        for (int w = 0; w < 8; ++w) s += red[w];
        g_pm[b*NCH_ + c] = ml;
        g_ps[b*NCH_ + c] = s;
    }
}

// ---- softmax combine ----
__global__ void k_smax2(float* __restrict__ out) {
    int b = threadIdx.x;
    if (b >= B_) return;
    float m = -1e30f;
    for (int c = 0; c < NCH_; ++c) m = fmaxf(m, g_pm[b*NCH_ + c]);
    float sum = 0.f;
    for (int c = 0; c < NCH_; ++c) sum += g_ps[b*NCH_ + c] * expf(g_pm[b*NCH_ + c] - m);
    g_gm[b] = m;
    g_ginv[b] = 1.f / sum;
    for (int j = 0; j < OOV_; ++j) out[(size_t)b*VEXT_ + V_ + j] = 1e-4f;
}

// ---- write prob_g ----
__global__ __launch_bounds__(256) void k_smax3(float* __restrict__ out) {
    const int b = blockIdx.y, c = blockIdx.x, tid = threadIdx.x;
    const int i0 = c * 4096;
    const float m = g_gm[b], inv = g_ginv[b];
    for (int t = tid; t < 4096; t += 256) {
        int i = i0 + t;
        if (i < V_) out[(size_t)b*VEXT_ + i] = expf(g_score_g[(size_t)b*V_ + i] - m) * inv;
    }
}

// ---- prob_c + rowsums ----
__global__ void k_rowsums(const int* __restrict__ eidx) {
    int gid = blockIdx.x*blockDim.x + threadIdx.x;
    if (gid < M_) {
        int b = gid >> 11;
        float pc = expf(g_score_c[gid] - g_gm[b]) * g_ginv[b];
        g_prob_c[gid] = pc;
        atomicAdd(&g_rowsums[(size_t)b*VEXT_ + eidx[gid]], pc);
    }
}

// ---- final scatter; collect matches ----
__global__ void k_final(const int* __restrict__ eidx, const int* __restrict__ input_idx,
                        float* __restrict__ out)
{
    int gid = blockIdx.x*blockDim.x + threadIdx.x;
    if (gid >= M_) return;
    int b = gid >> 11;
    int idx = eidx[gid];
    float pc = g_prob_c[gid];
    float attn = pc;
    if (g_counts[idx] > 1) attn = pc * g_rowsums[(size_t)b*VEXT_ + idx];
    atomicAdd(&out[(size_t)b*VEXT_ + idx], attn);

    if (idx == input_idx[b]) {
        int rs = g_rs[b];
        float f = (rs > 1) ? (1.f / (float)rs) : 1.f;
        int slot = atomicAdd(&g_mcount, 1);
        if (slot < 8192) { g_mlist[slot] = gid; g_mval[slot] = pc * f; }
    }
}

// ---- weighted_out from sparse match list ----
__global__ __launch_bounds__(512) void k_weighted(const float* __restrict__ enc,
                                                  float* __restrict__ out)
{
    const int d = threadIdx.x;
    const int n = g_mcount < 8192 ? g_mcount : 8192;
    for (int e = 0; e < n; ++e) {
        int gid = g_mlist[e];
        int b = gid >> 11;
        out[OFF_W + b*512 + d] += g_mval[e] * enc[(size_t)gid*KD_ + d];
    }
}

extern "C" void kernel_launch(void* const* d_in, const int* in_sizes, int n_in,
                              void* d_out, int out_size)
{
    const int*   input_idx = (const int*)  d_in[0];
    const float* encoded   = (const float*)d_in[1];
    const int*   eidx      = (const int*)  d_in[2];
    const float* prev_st   = (const float*)d_in[3];
    const float* weighted  = (const float*)d_in[4];
    const float* embed     = (const float*)d_in[6];
    const float* w_ih      = (const float*)d_in[7];
    const float* w_hh      = (const float*)d_in[8];
    const float* b_ih      = (const float*)d_in[9];
    const float* b_hh      = (const float*)d_in[10];
    const float* Wo_w      = (const float*)d_in[11];
    const float* Wo_b      = (const float*)d_in[12];
    const float* Wc_w      = (const float*)d_in[13];
    const float* Wc_b      = (const float*)d_in[14];
    float* out = (float*)d_out;

    cudaFuncSetAttribute(k_score_c, cudaFuncAttributeMaxDynamicSharedMemorySize, SC_SMEM);
    cudaFuncSetAttribute(k_score_g, cudaFuncAttributeMaxDynamicSharedMemorySize, SG_SMEM);

    // k_score_c at launch index 3 (ncu profiling slot)
    k_prep<<<4096, 256>>>(input_idx, embed, weighted, prev_st, Wc_w, out);
    k_gru_gemm<<<dim3(96, 2), 256>>>(w_ih, w_hh);
    k_gates<<<B_, H_>>>(b_ih, b_hh, prev_st, out);
    k_score_c<<<(M_/128)*2, 256, SC_SMEM>>>(encoded, Wc_b);
    k_counts<<<M_/256, 256>>>(eidx, input_idx);
    k_score_g<<<(V_ + 63)/64, 256, SG_SMEM>>>(Wo_w, Wo_b);
    k_smax1<<<dim3(NCH_, B_), 256>>>();
    k_smax2<<<1, 32>>>(out);
    k_smax3<<<dim3(NCH_, B_), 256>>>(out);
    k_rowsums<<<M_/256, 256>>>(eidx);
    k_final<<<M_/256, 256>>>(eidx, input_idx, out);
    k_weighted<<<1, 512>>>(encoded, out);
}